// round 2
// baseline (speedup 1.0000x reference)
#include <cuda_runtime.h>
#include <cuda_bf16.h>

#define BATCH 4096
#define NHID  512
#define BR    32

// One block per sample, 3 warps (one per tree level).
// Warp layout: lane = (g, ci) with g = lane>>3 (h-phase 0..3), ci = lane&7
// (column quad: columns 4*ci .. 4*ci+3).
// Lane loads float4 of W row h (its 4 columns) for h = g, g+4, g+8, ...
// -> 128 LDG.128 per warp instead of 512 LDG.32 (same bytes, 4x fewer
//    LSU dispatches, which round-1 ncu showed to be the binding floor).
__global__ __launch_bounds__(96, 21)
void hs_kernel(const float* __restrict__ x,
               const int* __restrict__ labels,
               const float* __restrict__ W,
               float* __restrict__ out)
{
    __shared__ float xs[NHID];
    __shared__ float pshared[3];

    const int b    = blockIdx.x;
    const int tid  = threadIdx.x;
    const int warp = tid >> 5;
    const int lane = tid & 31;

    // Stage x[b] in smem (128 float4)
    {
        const float4* xg = reinterpret_cast<const float4*>(x + (size_t)b * NHID);
        float4* xsv = reinterpret_cast<float4*>(xs);
        for (int i = tid; i < NHID / 4; i += 96) xsv[i] = xg[i];
    }
    __syncthreads();

    const int lab = labels[b];

    // Per-level node index and step (BR=32 -> shifts/masks)
    int node, step;
    if (warp == 0)      { node = 0;                step = lab >> 10; }
    else if (warp == 1) { node = 1  + (lab >> 10); step = (lab >> 5) & 31; }
    else                { node = 33 + (lab >> 5);  step = lab & 31; }

    const int g  = lane >> 3;   // h-phase
    const int ci = lane & 7;    // column quad

    // W[node] viewed as float4: row h has 8 float4s (32 cols)
    const float4* __restrict__ Wv =
        reinterpret_cast<const float4*>(W) + (size_t)node * (NHID * BR / 4) + ci;

    float4 acc = make_float4(0.f, 0.f, 0.f, 0.f);
    #pragma unroll 4
    for (int h = g; h < NHID; h += 4) {
        float4 w  = __ldg(Wv + h * 8);
        float  xv = xs[h];                 // broadcast within 8-lane group
        acc.x = fmaf(xv, w.x, acc.x);
        acc.y = fmaf(xv, w.y, acc.y);
        acc.z = fmaf(xv, w.z, acc.z);
        acc.w = fmaf(xv, w.w, acc.w);
    }

    // Fold the 4 h-phases: lanes l, l^8, l^16, l^24 share the same ci
    #pragma unroll
    for (int o = 8; o <= 16; o <<= 1) {
        acc.x += __shfl_xor_sync(0xffffffffu, acc.x, o);
        acc.y += __shfl_xor_sync(0xffffffffu, acc.y, o);
        acc.z += __shfl_xor_sync(0xffffffffu, acc.z, o);
        acc.w += __shfl_xor_sync(0xffffffffu, acc.w, o);
    }
    // Now every lane with column-quad ci holds final logits for cols 4ci..4ci+3.

    // Softmax over 32 logits spread as 8 lanes x 4 components
    float m = fmaxf(fmaxf(acc.x, acc.y), fmaxf(acc.z, acc.w));
    #pragma unroll
    for (int o = 1; o <= 4; o <<= 1) m = fmaxf(m, __shfl_xor_sync(0xffffffffu, m, o));

    float4 e;
    e.x = __expf(acc.x - m);
    e.y = __expf(acc.y - m);
    e.z = __expf(acc.z - m);
    e.w = __expf(acc.w - m);
    float s = (e.x + e.y) + (e.z + e.w);
    #pragma unroll
    for (int o = 1; o <= 4; o <<= 1) s += __shfl_xor_sync(0xffffffffu, s, o);

    // Pick the step column: quad ct = step>>2, component j = step&3
    const int ct = step >> 2;
    const int j  = step & 3;
    float esel = (j == 0) ? e.x : (j == 1) ? e.y : (j == 2) ? e.z : e.w;
    float pstep = __shfl_sync(0xffffffffu, esel, ct) / s;

    if (lane == 0) pshared[warp] = pstep;
    __syncthreads();
    if (tid == 0) out[b] = pshared[0] * pshared[1] * pshared[2];
}

extern "C" void kernel_launch(void* const* d_in, const int* in_sizes, int n_in,
                              void* d_out, int out_size)
{
    const float* x      = (const float*)d_in[0];   // inputs [4096, 512] f32
    const int*   labels = (const int*)d_in[1];     // labels [4096] i32
    const float* W      = (const float*)d_in[2];   // W [1057, 512, 32] f32
    float*       out    = (float*)d_out;           // [4096] f32

    hs_kernel<<<BATCH, 96>>>(x, labels, W, out);
}